// round 11
// baseline (speedup 1.0000x reference)
#include <cuda_runtime.h>
#include <cstdint>

#define Tn 2048
#define Hn 256
#define Bn 256
#define Pn 24

#define NT      512       // 16 warps: jhalf = wid&1, kslot = wid>>1
#define KSLOTS  8
#define KB_PER  32                       // k-rows per k-block
#define ITS_REG 20                       // first 20 k of each block in registers
#define ITS_SM  (KB_PER - ITS_REG)       // last 12 k of each block in smem
#define WSM_ROWS (KSLOTS * ITS_SM)       // 96 rows in smem

// 2*log2(e): folded into W/b so tanh needs only EX2 (no pre-multiply)
#define SCALE 2.8853900817779268f

typedef unsigned long long ull;

// Shared memory layout (float offsets)
//  Wt   : [96][256] rows (kslot*12 + i) <-> k = kslot*32 + 20 + i = 24576 floats ( 96 KB)
//  hb   : [2][256] batch-major hidden state                        =   512 floats (  2 KB)
//  red0 : [16][256] partials buffer A                              =  4096 floats ( 16 KB)
//  red1 : [16][256] partials buffer B                              =  4096 floats ( 16 KB)
//  xs   : [2][2048] cached x rows                                  =  4096 floats ( 16 KB)
#define OFF_W    0
#define OFF_H    24576
#define OFF_RED0 25088
#define OFF_RED1 29184
#define OFF_X    33280
#define SMEM_FLOATS 37376
#define SMEM_BYTES (SMEM_FLOATS * 4)

__device__ __forceinline__ void ffma2(ull& a, ull b, ull c) {
    asm("fma.rn.f32x2 %0, %1, %2, %0;" : "+l"(a) : "l"(b), "l"(c));
}
__device__ __forceinline__ ull packf2(float lo, float hi) {
    ull r; asm("mov.b64 %0, {%1, %2};" : "=l"(r) : "f"(lo), "f"(hi)); return r;
}
__device__ __forceinline__ ull dupf2(float v) {
    ull r; asm("mov.b64 %0, {%1, %1};" : "=l"(r) : "f"(v)); return r;
}
__device__ __forceinline__ float2 u2f(ull v) {
    float2 r; asm("mov.b64 {%0, %1}, %2;" : "=f"(r.x), "=f"(r.y) : "l"(v)); return r;
}
__device__ __forceinline__ void nbar_sync(int id, int cnt) {
    asm volatile("bar.sync %0, %1;" :: "r"(id), "r"(cnt) : "memory");
}
__device__ __forceinline__ void nbar_arrive(int id, int cnt) {
    asm volatile("bar.arrive %0, %1;" :: "r"(id), "r"(cnt) : "memory");
}
// tanh with pre-scaled argument: input raw = 2*log2(e)*z; returns tanh(z).
// tanh(z) = 1 - 2/(2^raw + 1). EX2 + ADD + RCP + FFMA. Saturates correctly.
__device__ __forceinline__ float tanh_scaled(float raw) {
    float e, r;
    asm("ex2.approx.f32 %0, %1;" : "=f"(e) : "f"(raw));
    float ep1 = e + 1.0f;
    asm("rcp.approx.f32 %0, %1;" : "=f"(r) : "f"(ep1));
    return fmaf(-2.0f, r, 1.0f);
}

__global__ void __launch_bounds__(NT, 1)
rnn_persistent_kernel(const float* __restrict__ x,
                      const float* __restrict__ W_ih,
                      const float* __restrict__ W_hh,
                      const float* __restrict__ b_ih,
                      const float* __restrict__ b_hh,
                      const float* __restrict__ W_out,
                      const float* __restrict__ b_out,
                      float* __restrict__ out)
{
    extern __shared__ float sm[];
    float* Wt  = sm + OFF_W;
    float* hb  = sm + OFF_H;
    float* xs  = sm + OFF_X;

    const int tid   = threadIdx.x;
    const int lane  = tid & 31;
    const int wid   = tid >> 5;
    const int jhalf = wid & 1;          // half of j-rows this warp covers
    const int kslot = wid >> 1;         // contiguous k-block [kslot*32, +32)
    const int kbase = kslot * KB_PER;
    const int j0    = jhalf * 128 + lane * 4;
    const int b0    = blockIdx.x * 2;
    const int fb    = tid >> 8;         // finalize: batch  (= wid>>3)
    const int fj    = tid & 255;        // finalize: j row  (seg = wid&7)
    // Named-barrier roles for the finalize(h seg) -> phaseB(consume seg) edge.
    // Barrier (1+s): producers = warps {s, s+8} (write h seg s, both batches),
    // consumers = warps {2s, 2s+1} (phase B reads h seg s). Warp 0 and warp 15
    // are both producer and consumer of the same barrier -> single bar.sync.
    const int pbar  = 1 + (wid & 7);    // barrier this warp produces for
    const int cbar  = 1 + (wid >> 1);   // barrier this warp consumes from
    const int pcnt  = ((wid & 7) == 0 || (wid & 7) == 7) ? 96 : 128;
    const int ccnt  = ((wid >> 1) == 0 || (wid >> 1) == 7) ? 96 : 128;
    const bool both = (pbar == cbar);   // wid 0 and wid 15

    // ---------------- init ----------------
    for (int i = tid; i < Tn; i += NT) {
        xs[i]      = x[(size_t)b0 * Tn + i];
        xs[Tn + i] = x[(size_t)(b0 + 1) * Tn + i];
    }
    // smem W rows (pre-scaled): row r -> k = (r/ITS_SM)*32 + ITS_REG + (r%ITS_SM)
    for (int idx = tid; idx < 256 * (WSM_ROWS / 4); idx += NT) {
        int j  = idx / (WSM_ROWS / 4);
        int rc = idx % (WSM_ROWS / 4);
        #pragma unroll
        for (int q = 0; q < 4; ++q) {
            int r = rc * 4 + q;
            int k = (r / ITS_SM) * KB_PER + ITS_REG + (r % ITS_SM);
            Wt[r * 256 + j] = W_hh[j * Hn + k] * SCALE;
        }
    }
    // register W (pre-scaled): k = kbase + i, i in [0,20), packed as j-pairs
    ull wr0[ITS_REG], wr1[ITS_REG];
    #pragma unroll
    for (int i = 0; i < ITS_REG; ++i) {
        int k = kbase + i;
        wr0[i] = packf2(W_hh[(j0 + 0) * Hn + k] * SCALE, W_hh[(j0 + 1) * Hn + k] * SCALE);
        wr1[i] = packf2(W_hh[(j0 + 2) * Hn + k] * SCALE, W_hh[(j0 + 3) * Hn + k] * SCALE);
    }
    const float c1 = W_ih[fj] * SCALE;
    const float c0 = (b_ih[fj] + b_hh[fj]) * SCALE;
    if (tid < 512) hb[tid] = 0.f;
    // zero both red buffers: first finalize then yields h_1 = tanh(xp_0)
    for (int i = tid; i < 8192; i += NT) sm[OFF_RED0 + i] = 0.f;
    __syncthreads();

    float* redRead  = sm + OFF_RED0;
    float* redWrite = sm + OFF_RED1;

    // ---------------- recurrence ----------------
    // iter t: finalize h_{t+1} from redRead (= W*h_t) and xp[t]; then phase B
    // computes W*h_{t+1} partials into redWrite. The finalize->phaseB edge uses
    // per-segment named barriers (2 producers per consumer) instead of a full
    // CTA barrier; the phaseB->finalize edge keeps one __syncthreads.
    for (int t = 0; t < Tn; ++t) {
        // ---- finalize: thread (fb, fj) reduces its 8 k-slot partials (R7 form)
        {
            float r0 = redRead[(0 * 2 + fb) * 256 + fj];
            float r1 = redRead[(1 * 2 + fb) * 256 + fj];
            float r2 = redRead[(2 * 2 + fb) * 256 + fj];
            float r3 = redRead[(3 * 2 + fb) * 256 + fj];
            float r4 = redRead[(4 * 2 + fb) * 256 + fj];
            float r5 = redRead[(5 * 2 + fb) * 256 + fj];
            float r6 = redRead[(6 * 2 + fb) * 256 + fj];
            float r7 = redRead[(7 * 2 + fb) * 256 + fj];
            float s  = ((r0 + r1) + (r2 + r3)) + ((r4 + r5) + (r6 + r7));
            float xv = xs[fb * Tn + t];
            float h  = tanh_scaled(fmaf(xv, c1, c0) + s);
            hb[fb * 256 + fj] = h;   // contiguous store, 1 wavefront
        }
        // ---- targeted sync: signal own segment done, wait for consumed segment
        if (both) {
            nbar_sync(pbar, pcnt);
        } else {
            nbar_arrive(pbar, pcnt);
            nbar_sync(cbar, ccnt);
        }

        // ---- phase B (R7 body, unchanged) ----
        ull a00 = 0, a01 = 0, a10 = 0, a11 = 0;    // a{jpair}{batch}
        const float4* h0p = (const float4*)(hb + kbase);
        const float4* h1p = (const float4*)(hb + 256 + kbase);
        const float*  wp  = &Wt[(kslot * ITS_SM) * 256 + j0];

        auto do_reg = [&]() {
            #pragma unroll
            for (int blk = 0; blk < ITS_REG / 4; ++blk) {
                float4 hv0 = h0p[blk];                 // broadcast LDS.128
                float4 hv1 = h1p[blk];
                #pragma unroll
                for (int c = 0; c < 4; ++c) {
                    int i = blk * 4 + c;
                    ull d0 = dupf2(((const float*)&hv0)[c]);
                    ull d1 = dupf2(((const float*)&hv1)[c]);
                    ffma2(a00, wr0[i], d0);
                    ffma2(a01, wr0[i], d1);
                    ffma2(a10, wr1[i], d0);
                    ffma2(a11, wr1[i], d1);
                }
            }
        };
        auto do_smem = [&]() {
            #pragma unroll
            for (int blk = 0; blk < ITS_SM / 4; ++blk) {
                float4 hv0 = h0p[ITS_REG / 4 + blk];
                float4 hv1 = h1p[ITS_REG / 4 + blk];
                #pragma unroll
                for (int c = 0; c < 4; ++c) {
                    int r = blk * 4 + c;
                    ulonglong2 wv = *(const ulonglong2*)(wp + r * 256);  // contiguous LDS.128
                    ull d0 = dupf2(((const float*)&hv0)[c]);
                    ull d1 = dupf2(((const float*)&hv1)[c]);
                    ffma2(a00, wv.x, d0);
                    ffma2(a01, wv.x, d1);
                    ffma2(a10, wv.y, d0);
                    ffma2(a11, wv.y, d1);
                }
            }
        };
        // Coarse desync (R7-validated): half the warps hit the crossbar first.
        if (jhalf == 0) { do_reg(); do_smem(); }
        else            { do_smem(); do_reg(); }

        // k-slot partials into the write buffer
        {
            float2 p00 = u2f(a00), p10 = u2f(a10);
            float2 p01 = u2f(a01), p11 = u2f(a11);
            *(float4*)&redWrite[(kslot * 2 + 0) * 256 + j0] = make_float4(p00.x, p00.y, p10.x, p10.y);
            *(float4*)&redWrite[(kslot * 2 + 1) * 256 + j0] = make_float4(p01.x, p01.y, p11.x, p11.y);
        }
        // swap buffers; single CTA-wide barrier per step
        float* tmp = redRead; redRead = redWrite; redWrite = tmp;
        __syncthreads();
    }

    // hb holds h_T (written in the last finalize, fenced by the final barrier)

    // ---------------- output head ----------------
    if (tid < 2 * Pn) {
        int b = tid / Pn;
        int p = tid % Pn;
        float s = b_out[p];
        const float* wrow = &W_out[p * Hn];
        const float* hrow = &hb[b * 256];
        #pragma unroll 8
        for (int h = 0; h < Hn; ++h)
            s = fmaf(hrow[h], wrow[h], s);
        out[(size_t)(b0 + b) * Pn + p] = s;
    }
}

extern "C" void kernel_launch(void* const* d_in, const int* in_sizes, int n_in,
                              void* d_out, int out_size) {
    const float* x     = (const float*)d_in[0];
    const float* W_ih  = (const float*)d_in[1];
    const float* W_hh  = (const float*)d_in[2];
    const float* b_ih  = (const float*)d_in[3];
    const float* b_hh  = (const float*)d_in[4];
    const float* W_out = (const float*)d_in[5];
    const float* b_out = (const float*)d_in[6];
    float* out = (float*)d_out;

    cudaFuncSetAttribute(rnn_persistent_kernel,
                         cudaFuncAttributeMaxDynamicSharedMemorySize, SMEM_BYTES);
    rnn_persistent_kernel<<<Bn / 2, NT, SMEM_BYTES>>>(
        x, W_ih, W_hh, b_ih, b_hh, W_out, b_out, out);
}

// round 12
// speedup vs baseline: 1.2298x; 1.2298x over previous
#include <cuda_runtime.h>
#include <cstdint>

#define Tn 2048
#define Hn 256
#define Bn 256
#define Pn 24

#define NT      512       // 16 warps: jhalf = wid&1, kslot = wid>>1
#define KSLOTS  8
#define KB_PER  32                       // k-rows per k-block
#define ITS_REG 20                       // first 20 k of each block in registers
#define ITS_SM  (KB_PER - ITS_REG)       // last 12 k of each block in smem
#define WSM_ROWS (KSLOTS * ITS_SM)       // 96 rows in smem

// 2*log2(e): folded into W/b so tanh needs only EX2 (no pre-multiply)
#define SCALE 2.8853900817779268f

typedef unsigned long long ull;

// Shared memory layout (float offsets)
//  Wt  : [96][256] rows (kslot*12 + i) <-> k = kslot*32 + 20 + i  = 24576 floats (96 KB)
//  hb  : [2][256] batch-major hidden state                         =   512 floats ( 2 KB)
//  red : [16][256] (kslot*2 + b) partials                          =  4096 floats (16 KB)
//  xs  : [2][2048] cached x rows                                   =  4096 floats (16 KB)
#define OFF_W   0
#define OFF_H   24576
#define OFF_RED 25088
#define OFF_X   29184
#define SMEM_FLOATS 33280
#define SMEM_BYTES (SMEM_FLOATS * 4)

__device__ __forceinline__ void ffma2(ull& a, ull b, ull c) {
    asm("fma.rn.f32x2 %0, %1, %2, %0;" : "+l"(a) : "l"(b), "l"(c));
}
__device__ __forceinline__ ull packf2(float lo, float hi) {
    ull r; asm("mov.b64 %0, {%1, %2};" : "=l"(r) : "f"(lo), "f"(hi)); return r;
}
__device__ __forceinline__ ull dupf2(float v) {
    ull r; asm("mov.b64 %0, {%1, %1};" : "=l"(r) : "f"(v)); return r;
}
__device__ __forceinline__ float2 u2f(ull v) {
    float2 r; asm("mov.b64 {%0, %1}, %2;" : "=f"(r.x), "=f"(r.y) : "l"(v)); return r;
}
// tanh with pre-scaled argument: input raw = 2*log2(e)*z; returns tanh(z).
// tanh(z) = 1 - 2/(2^raw + 1). EX2 + ADD + RCP + FFMA. Saturates correctly.
__device__ __forceinline__ float tanh_scaled(float raw) {
    float e, r;
    asm("ex2.approx.f32 %0, %1;" : "=f"(e) : "f"(raw));
    float ep1 = e + 1.0f;
    asm("rcp.approx.f32 %0, %1;" : "=f"(r) : "f"(ep1));
    return fmaf(-2.0f, r, 1.0f);
}

__global__ void __launch_bounds__(NT, 1)
rnn_persistent_kernel(const float* __restrict__ x,
                      const float* __restrict__ W_ih,
                      const float* __restrict__ W_hh,
                      const float* __restrict__ b_ih,
                      const float* __restrict__ b_hh,
                      const float* __restrict__ W_out,
                      const float* __restrict__ b_out,
                      float* __restrict__ out)
{
    extern __shared__ float sm[];
    float* Wt  = sm + OFF_W;
    float* hb  = sm + OFF_H;
    float* red = sm + OFF_RED;
    float* xs  = sm + OFF_X;

    const int tid   = threadIdx.x;
    const int lane  = tid & 31;
    const int wid   = tid >> 5;
    const int jhalf = wid & 1;          // half of j-rows this warp covers
    const int kslot = wid >> 1;         // contiguous k-block [kslot*32, +32)
    const int kbase = kslot * KB_PER;
    const int j0    = jhalf * 128 + lane * 4;
    const int b0    = blockIdx.x * 2;
    const int fb    = tid >> 8;         // finalize: batch
    const int fj    = tid & 255;        // finalize: j row

    // ---------------- init ----------------
    for (int i = tid; i < Tn; i += NT) {
        xs[i]      = x[(size_t)b0 * Tn + i];
        xs[Tn + i] = x[(size_t)(b0 + 1) * Tn + i];
    }
    // smem W rows (pre-scaled): row r -> k = (r/ITS_SM)*32 + ITS_REG + (r%ITS_SM)
    for (int idx = tid; idx < 256 * (WSM_ROWS / 4); idx += NT) {
        int j  = idx / (WSM_ROWS / 4);
        int rc = idx % (WSM_ROWS / 4);
        #pragma unroll
        for (int q = 0; q < 4; ++q) {
            int r = rc * 4 + q;
            int k = (r / ITS_SM) * KB_PER + ITS_REG + (r % ITS_SM);
            Wt[r * 256 + j] = W_hh[j * Hn + k] * SCALE;
        }
    }
    // register W (pre-scaled): k = kbase + i, i in [0,20), packed as j-pairs
    ull wr0[ITS_REG], wr1[ITS_REG];
    #pragma unroll
    for (int i = 0; i < ITS_REG; ++i) {
        int k = kbase + i;
        wr0[i] = packf2(W_hh[(j0 + 0) * Hn + k] * SCALE, W_hh[(j0 + 1) * Hn + k] * SCALE);
        wr1[i] = packf2(W_hh[(j0 + 2) * Hn + k] * SCALE, W_hh[(j0 + 3) * Hn + k] * SCALE);
    }
    const float c1 = W_ih[fj] * SCALE;
    const float c0 = (b_ih[fj] + b_hh[fj]) * SCALE;
    if (tid < 512) hb[tid] = 0.f;
    __syncthreads();

    // ---------------- recurrence ----------------
    for (int t = 0; t < Tn; ++t) {
        // Hoisted x-projection: overlaps with phase B, removing an LDS + FFMA
        // from the post-barrier finalize chain.
        const float xc = fmaf(xs[fb * Tn + t], c1, c0);

        ull a00 = 0, a01 = 0, a10 = 0, a11 = 0;    // a{jpair}{batch}
        const float4* h0p = (const float4*)(hb + kbase);
        const float4* h1p = (const float4*)(hb + 256 + kbase);
        const float*  wp  = &Wt[(kslot * ITS_SM) * 256 + j0];

        // Register-W segment (fma-heavy) — contiguous so ptxas batches loads.
        auto do_reg = [&]() {
            #pragma unroll
            for (int blk = 0; blk < ITS_REG / 4; ++blk) {
                float4 hv0 = h0p[blk];                 // broadcast LDS.128
                float4 hv1 = h1p[blk];
                #pragma unroll
                for (int c = 0; c < 4; ++c) {
                    int i = blk * 4 + c;
                    ull d0 = dupf2(((const float*)&hv0)[c]);
                    ull d1 = dupf2(((const float*)&hv1)[c]);
                    ffma2(a00, wr0[i], d0);
                    ffma2(a01, wr0[i], d1);
                    ffma2(a10, wr1[i], d0);
                    ffma2(a11, wr1[i], d1);
                }
            }
        };
        // Smem-W segment (crossbar-heavy) — contiguous load stream for MLP.
        auto do_smem = [&]() {
            #pragma unroll
            for (int blk = 0; blk < ITS_SM / 4; ++blk) {
                float4 hv0 = h0p[ITS_REG / 4 + blk];
                float4 hv1 = h1p[ITS_REG / 4 + blk];
                #pragma unroll
                for (int c = 0; c < 4; ++c) {
                    int r = blk * 4 + c;
                    ulonglong2 wv = *(const ulonglong2*)(wp + r * 256);  // contiguous LDS.128
                    ull d0 = dupf2(((const float*)&hv0)[c]);
                    ull d1 = dupf2(((const float*)&hv1)[c]);
                    ffma2(a00, wv.x, d0);
                    ffma2(a01, wv.x, d1);
                    ffma2(a10, wv.y, d0);
                    ffma2(a11, wv.y, d1);
                }
            }
        };
        // Coarse desync (R7-validated): half the warps hit the crossbar first,
        // half the fma pipe first, smoothing crossbar demand across the phase.
        if (jhalf == 0) { do_reg(); do_smem(); }
        else            { do_smem(); do_reg(); }

        // k-slot partials
        {
            float2 p00 = u2f(a00), p10 = u2f(a10);
            float2 p01 = u2f(a01), p11 = u2f(a11);
            *(float4*)&red[(kslot * 2 + 0) * 256 + j0] = make_float4(p00.x, p00.y, p10.x, p10.y);
            *(float4*)&red[(kslot * 2 + 1) * 256 + j0] = make_float4(p01.x, p01.y, p11.x, p11.y);
        }
        __syncthreads();

        // finalize: thread (fb, fj) reduces its 8 k-slot partials (two chains).
        {
            float s0 = red[(0 * 2 + fb) * 256 + fj];
            float s1 = red[(1 * 2 + fb) * 256 + fj];
            s0 += red[(2 * 2 + fb) * 256 + fj];
            s1 += red[(3 * 2 + fb) * 256 + fj];
            s0 += red[(4 * 2 + fb) * 256 + fj];
            s1 += red[(5 * 2 + fb) * 256 + fj];
            s0 += red[(6 * 2 + fb) * 256 + fj];
            s1 += red[(7 * 2 + fb) * 256 + fj];
            float h = tanh_scaled(xc + (s0 + s1));
            hb[fb * 256 + fj] = h;   // contiguous store, 1 wavefront
        }
        __syncthreads();
    }

    // ---------------- output head ----------------
    if (tid < 2 * Pn) {
        int b = tid / Pn;
        int p = tid % Pn;
        float s = b_out[p];
        const float* wrow = &W_out[p * Hn];
        const float* hrow = &hb[b * 256];
        #pragma unroll 8
        for (int h = 0; h < Hn; ++h)
            s = fmaf(hrow[h], wrow[h], s);
        out[(size_t)(b0 + b) * Pn + p] = s;
    }
}

extern "C" void kernel_launch(void* const* d_in, const int* in_sizes, int n_in,
                              void* d_out, int out_size) {
    const float* x     = (const float*)d_in[0];
    const float* W_ih  = (const float*)d_in[1];
    const float* W_hh  = (const float*)d_in[2];
    const float* b_ih  = (const float*)d_in[3];
    const float* b_hh  = (const float*)d_in[4];
    const float* W_out = (const float*)d_in[5];
    const float* b_out = (const float*)d_in[6];
    float* out = (float*)d_out;

    cudaFuncSetAttribute(rnn_persistent_kernel,
                         cudaFuncAttributeMaxDynamicSharedMemorySize, SMEM_BYTES);
    rnn_persistent_kernel<<<Bn / 2, NT, SMEM_BYTES>>>(
        x, W_ih, W_hh, b_ih, b_hh, W_out, b_out, out);
}